// round 2
// baseline (speedup 1.0000x reference)
#include <cuda_runtime.h>
#include <cstdint>

#define EMB 1024
#define BB  4
#define NQS 1024
#define NKS 2048
#define NH  16
#define HD  64

// ---------------- scratch (no allocations allowed) ----------------
__device__ float g_q [(size_t)BB * NQS * EMB];   // 16 MB
__device__ float g_k [(size_t)BB * NKS * EMB];   // 32 MB
__device__ float g_v [(size_t)BB * NKS * EMB];   // 32 MB
__device__ float g_ao[(size_t)BB * NQS * EMB];   // 16 MB (attention out, (b,q,h*d))

// =================================================================
// C[M,N] = A[M,K] @ W[N,K]^T + bias[N]
// 128x128 tile, BK=8, 256 threads, 8x8 micro-tile per thread.
// Both A and W are K-contiguous -> coalesced float4 global loads.
// =================================================================
__global__ __launch_bounds__(256)
void sgemm_nt(const float* __restrict__ A, const float* __restrict__ W,
              const float* __restrict__ bias, float* __restrict__ C,
              int M, int N, int K)
{
    __shared__ float As[8][128];
    __shared__ float Bs[8][128];

    const int tid = threadIdx.x;
    const int tx  = tid & 15;        // 0..15  -> n micro-block
    const int ty  = tid >> 4;        // 0..15  -> m micro-block
    const int m0  = blockIdx.y * 128;
    const int n0  = blockIdx.x * 128;

    const int lrow = tid >> 1;       // 0..127
    const int lcol = (tid & 1) * 4;  // 0 or 4

    float acc[8][8];
#pragma unroll
    for (int i = 0; i < 8; i++)
#pragma unroll
        for (int j = 0; j < 8; j++) acc[i][j] = 0.f;

    const float* Ap = A + (size_t)(m0 + lrow) * K + lcol;
    const float* Wp = W + (size_t)(n0 + lrow) * K + lcol;

    for (int k0 = 0; k0 < K; k0 += 8) {
        float4 a4 = *(const float4*)(Ap + k0);
        float4 b4 = *(const float4*)(Wp + k0);
        __syncthreads();             // protect As/Bs from previous iteration's readers
        As[lcol + 0][lrow] = a4.x; As[lcol + 1][lrow] = a4.y;
        As[lcol + 2][lrow] = a4.z; As[lcol + 3][lrow] = a4.w;
        Bs[lcol + 0][lrow] = b4.x; Bs[lcol + 1][lrow] = b4.y;
        Bs[lcol + 2][lrow] = b4.z; Bs[lcol + 3][lrow] = b4.w;
        __syncthreads();

#pragma unroll
        for (int kk = 0; kk < 8; kk++) {
            float af[8], bf[8];
            *(float4*)&af[0] = *(const float4*)&As[kk][ty * 8];
            *(float4*)&af[4] = *(const float4*)&As[kk][ty * 8 + 4];
            *(float4*)&bf[0] = *(const float4*)&Bs[kk][tx * 8];
            *(float4*)&bf[4] = *(const float4*)&Bs[kk][tx * 8 + 4];
#pragma unroll
            for (int i = 0; i < 8; i++)
#pragma unroll
                for (int j = 0; j < 8; j++)
                    acc[i][j] = fmaf(af[i], bf[j], acc[i][j]);
        }
    }

#pragma unroll
    for (int i = 0; i < 8; i++) {
        float* Cp = C + (size_t)(m0 + ty * 8 + i) * N + n0 + tx * 8;
#pragma unroll
        for (int j = 0; j < 8; j++)
            Cp[j] = acc[i][j] + bias[n0 + tx * 8 + j];
    }
}

// =================================================================
// Attention: per (q-block of 64, head, batch).
// Online (flash-style) softmax with log(multiplicity) added to logits.
// Q tile 64x64 resident in smem; K/V streamed in 64-key chunks.
// 256 threads as 16x16; each thread owns a 4x4 tile of S and of O.
// Dynamic smem: Qs,Ks,Vs,Ps (64x68 each) + Lm[64] = 69,888 B.
// =================================================================
#define ATTN_SMEM ((4 * 64 * 68 + 64) * 4)

__global__ __launch_bounds__(256)
void attn_kernel(const float* __restrict__ Q, const float* __restrict__ Kt,
                 const float* __restrict__ V, const float* __restrict__ mult,
                 float* __restrict__ O)
{
    extern __shared__ float sm[];
    float (*Qs)[68] = (float(*)[68])(sm);
    float (*Ks)[68] = (float(*)[68])(sm + 64 * 68);
    float (*Vs)[68] = (float(*)[68])(sm + 2 * 64 * 68);
    float (*Ps)[68] = (float(*)[68])(sm + 3 * 64 * 68);
    float* Lm = sm + 4 * 64 * 68;

    const int tid = threadIdx.x;
    const int tx  = tid & 15;   // key / d-col micro-block
    const int ty  = tid >> 4;   // query micro-block
    const int qb  = blockIdx.x;
    const int h   = blockIdx.y;
    const int b   = blockIdx.z;

    const float* qp = Q  + (size_t)(b * NQS + qb * 64) * EMB + h * HD;
    const float* kp = Kt + (size_t)b * NKS * EMB + h * HD;
    const float* vp = V  + (size_t)b * NKS * EMB + h * HD;

    // load Q tile (64 rows x 64 cols)
#pragma unroll
    for (int i = 0; i < 4; i++) {
        int idx = tid + i * 256;
        int r = idx >> 4, c = (idx & 15) * 4;
        *(float4*)&Qs[r][c] = *(const float4*)(qp + (size_t)r * EMB + c);
    }

    float acc[4][4];
    float mrun[4], lrun[4];
#pragma unroll
    for (int i = 0; i < 4; i++) {
        mrun[i] = -3.4e38f;
        lrun[i] = 0.f;
#pragma unroll
        for (int j = 0; j < 4; j++) acc[i][j] = 0.f;
    }

    for (int k0 = 0; k0 < NKS; k0 += 64) {
        __syncthreads();   // prior chunk's readers of Ks/Vs/Ps done
#pragma unroll
        for (int i = 0; i < 4; i++) {
            int idx = tid + i * 256;
            int r = idx >> 4, c = (idx & 15) * 4;
            *(float4*)&Ks[r][c] = *(const float4*)(kp + (size_t)(k0 + r) * EMB + c);
            *(float4*)&Vs[r][c] = *(const float4*)(vp + (size_t)(k0 + r) * EMB + c);
        }
        if (tid < 64) Lm[tid] = logf(mult[b * NKS + k0 + tid]);
        __syncthreads();

        // S = Qs @ Ks^T   (4x4 per thread)
        float s[4][4];
#pragma unroll
        for (int i = 0; i < 4; i++)
#pragma unroll
            for (int j = 0; j < 4; j++) s[i][j] = 0.f;

#pragma unroll 4
        for (int d = 0; d < 64; d += 4) {
            float4 a[4], bb[4];
#pragma unroll
            for (int i = 0; i < 4; i++) a[i]  = *(const float4*)&Qs[ty * 4 + i][d];
#pragma unroll
            for (int j = 0; j < 4; j++) bb[j] = *(const float4*)&Ks[tx * 4 + j][d];
#pragma unroll
            for (int i = 0; i < 4; i++)
#pragma unroll
                for (int j = 0; j < 4; j++) {
                    s[i][j] = fmaf(a[i].x, bb[j].x, s[i][j]);
                    s[i][j] = fmaf(a[i].y, bb[j].y, s[i][j]);
                    s[i][j] = fmaf(a[i].z, bb[j].z, s[i][j]);
                    s[i][j] = fmaf(a[i].w, bb[j].w, s[i][j]);
                }
        }

        // logits + online softmax (row stats replicated across the 16 tx lanes)
#pragma unroll
        for (int i = 0; i < 4; i++) {
#pragma unroll
            for (int j = 0; j < 4; j++)
                s[i][j] = s[i][j] * 0.125f + Lm[tx * 4 + j];

            float mx = fmaxf(fmaxf(s[i][0], s[i][1]), fmaxf(s[i][2], s[i][3]));
#pragma unroll
            for (int o = 8; o >= 1; o >>= 1)
                mx = fmaxf(mx, __shfl_xor_sync(0xffffffffu, mx, o));
            float mnew = fmaxf(mrun[i], mx);
            float corr = __expf(mrun[i] - mnew);   // first chunk: exp(-inf)=0
            float rs = 0.f;
#pragma unroll
            for (int j = 0; j < 4; j++) {
                s[i][j] = __expf(s[i][j] - mnew);
                rs += s[i][j];
            }
#pragma unroll
            for (int o = 8; o >= 1; o >>= 1)
                rs += __shfl_xor_sync(0xffffffffu, rs, o);
            lrun[i] = lrun[i] * corr + rs;
            mrun[i] = mnew;
#pragma unroll
            for (int j = 0; j < 4; j++) acc[i][j] *= corr;
#pragma unroll
            for (int j = 0; j < 4; j++) Ps[ty * 4 + i][tx * 4 + j] = s[i][j];
        }
        __syncthreads();

        // O += P @ V   (thread owns O rows ty*4.., d-cols tx*4..)
#pragma unroll 8
        for (int c = 0; c < 64; c++) {
            float4 v4 = *(const float4*)&Vs[c][tx * 4];
#pragma unroll
            for (int i = 0; i < 4; i++) {
                float p = Ps[ty * 4 + i][c];
                acc[i][0] = fmaf(p, v4.x, acc[i][0]);
                acc[i][1] = fmaf(p, v4.y, acc[i][1]);
                acc[i][2] = fmaf(p, v4.z, acc[i][2]);
                acc[i][3] = fmaf(p, v4.w, acc[i][3]);
            }
        }
    }

    // epilogue: normalize, write as (b, q, h*HD + d)
    float* op = O + (size_t)(b * NQS + qb * 64) * EMB + h * HD;
#pragma unroll
    for (int i = 0; i < 4; i++) {
        float inv = 1.f / lrun[i];
#pragma unroll
        for (int j = 0; j < 4; j++)
            op[(size_t)(ty * 4 + i) * EMB + tx * 4 + j] = acc[i][j] * inv;
    }
}

// =================================================================
extern "C" void kernel_launch(void* const* d_in, const int* in_sizes, int n_in,
                              void* d_out, int out_size)
{
    const float* query = (const float*)d_in[0];
    const float* key_  = (const float*)d_in[1];
    const float* value = (const float*)d_in[2];
    const float* mult  = (const float*)d_in[3];
    const float* wq_w  = (const float*)d_in[4];
    const float* wq_b  = (const float*)d_in[5];
    const float* wk_w  = (const float*)d_in[6];
    const float* wk_b  = (const float*)d_in[7];
    const float* wv_w  = (const float*)d_in[8];
    const float* wv_b  = (const float*)d_in[9];
    const float* wo_w  = (const float*)d_in[10];
    const float* wo_b  = (const float*)d_in[11];
    float* out = (float*)d_out;

    float *q, *k, *v, *ao;
    cudaGetSymbolAddress((void**)&q,  g_q);
    cudaGetSymbolAddress((void**)&k,  g_k);
    cudaGetSymbolAddress((void**)&v,  g_v);
    cudaGetSymbolAddress((void**)&ao, g_ao);

    cudaFuncSetAttribute(attn_kernel,
                         cudaFuncAttributeMaxDynamicSharedMemorySize, ATTN_SMEM);

    dim3 gq(EMB / 128, (BB * NQS) / 128);   // (8, 32)
    dim3 gk(EMB / 128, (BB * NKS) / 128);   // (8, 64)

    sgemm_nt<<<gq, 256>>>(query, wq_w, wq_b, q,  BB * NQS, EMB, EMB);
    sgemm_nt<<<gk, 256>>>(key_,  wk_w, wk_b, k,  BB * NKS, EMB, EMB);
    sgemm_nt<<<gk, 256>>>(value, wv_w, wv_b, v,  BB * NKS, EMB, EMB);

    dim3 ga(NQS / 64, NH, BB);              // (16, 16, 4)
    attn_kernel<<<ga, 256, ATTN_SMEM>>>(q, k, v, mult, ao);

    sgemm_nt<<<gq, 256>>>(ao, wo_w, wo_b, out, BB * NQS, EMB, EMB);
}

// round 4
// speedup vs baseline: 1.3061x; 1.3061x over previous
#include <cuda_runtime.h>
#include <cuda_bf16.h>
#include <cstdint>

#define EMB 1024
#define BB  4
#define NQS 1024
#define NKS 2048
#define NH  16
#define HD  64

// ---------------- scratch (no allocations allowed) ----------------
__device__ float g_q [(size_t)BB * NQS * EMB];
__device__ float g_k [(size_t)BB * NKS * EMB];
__device__ float g_v [(size_t)BB * NKS * EMB];
__device__ float g_ao[(size_t)BB * NQS * EMB];

__device__ __nv_bfloat16 g_qh [(size_t)BB * NQS * EMB];
__device__ __nv_bfloat16 g_ql [(size_t)BB * NQS * EMB];
__device__ __nv_bfloat16 g_kh [(size_t)BB * NKS * EMB];
__device__ __nv_bfloat16 g_kl [(size_t)BB * NKS * EMB];
__device__ __nv_bfloat16 g_vh [(size_t)BB * NKS * EMB];
__device__ __nv_bfloat16 g_vl [(size_t)BB * NKS * EMB];
__device__ __nv_bfloat16 g_aoh[(size_t)BB * NQS * EMB];
__device__ __nv_bfloat16 g_aol[(size_t)BB * NQS * EMB];
__device__ __nv_bfloat16 g_wh [4][(size_t)EMB * EMB];
__device__ __nv_bfloat16 g_wl [4][(size_t)EMB * EMB];

// ============== split fp32 -> bf16 hi + bf16 lo ==================
__global__ __launch_bounds__(256)
void split_kernel(const float* __restrict__ x, __nv_bfloat16* __restrict__ hi,
                  __nv_bfloat16* __restrict__ lo, int n4)
{
    int i = blockIdx.x * blockDim.x + threadIdx.x;
    if (i >= n4) return;
    float4 v = ((const float4*)x)[i];
    __nv_bfloat16 hx = __float2bfloat16(v.x), hy = __float2bfloat16(v.y);
    __nv_bfloat16 hz = __float2bfloat16(v.z), hw = __float2bfloat16(v.w);
    __nv_bfloat162 h0; h0.x = hx; h0.y = hy;
    __nv_bfloat162 h1; h1.x = hz; h1.y = hw;
    __nv_bfloat162 l0, l1;
    l0.x = __float2bfloat16(v.x - __bfloat162float(hx));
    l0.y = __float2bfloat16(v.y - __bfloat162float(hy));
    l1.x = __float2bfloat16(v.z - __bfloat162float(hz));
    l1.y = __float2bfloat16(v.w - __bfloat162float(hw));
    ((__nv_bfloat162*)hi)[2 * i] = h0; ((__nv_bfloat162*)hi)[2 * i + 1] = h1;
    ((__nv_bfloat162*)lo)[2 * i] = l0; ((__nv_bfloat162*)lo)[2 * i + 1] = l1;
}

// ============== bf16x3 mma.sync GEMM: C = A @ W^T + bias =========
// 128x128 CTA tile, K-chunk 64, 8 warps (4m x 2n), warp tile 32x64.
// mma.sync.m16n8k16.row.col f32.bf16.bf16.f32 (portable ISA, no 'a').
#define LDT 72                         // smem row stride in bf16 (conflict-free)
#define TILE_ELEMS (128 * LDT)
#define G_SMEM (4 * TILE_ELEMS * 2)    // Ah, Al, Wh, Wl = 73728 B

#define MMA16816(d, a, b0, b1)                                            \
    asm volatile("mma.sync.aligned.m16n8k16.row.col.f32.bf16.bf16.f32 "   \
                 "{%0,%1,%2,%3}, {%4,%5,%6,%7}, {%8,%9}, {%0,%1,%2,%3};"  \
                 : "+f"((d)[0]), "+f"((d)[1]), "+f"((d)[2]), "+f"((d)[3]) \
                 : "r"((a)[0]), "r"((a)[1]), "r"((a)[2]), "r"((a)[3]),    \
                   "r"(b0), "r"(b1))

__device__ __forceinline__ uint32_t ld_u32s(const __nv_bfloat16* p) {
    return *(const uint32_t*)p;
}

__device__ __forceinline__ void copy_tile(__nv_bfloat16* dst,
                                          const __nv_bfloat16* src,
                                          int ldk, int tid)
{
#pragma unroll
    for (int i = 0; i < 4; i++) {
        int idx = tid + i * 256;
        int r = idx >> 3, c8 = idx & 7;          // 128 rows x 8 chunks of 8 bf16
        float4 v = *(const float4*)(src + (size_t)r * ldk + c8 * 8);
        *(float4*)(dst + r * LDT + c8 * 8) = v;
    }
}

__global__ __launch_bounds__(256)
void gemm_bf16x3(const __nv_bfloat16* __restrict__ Ah, const __nv_bfloat16* __restrict__ Al,
                 const __nv_bfloat16* __restrict__ Wh, const __nv_bfloat16* __restrict__ Wl,
                 const float* __restrict__ bias, float* __restrict__ C,
                 int M, int N, int K)
{
    extern __shared__ __nv_bfloat16 smb[];
    __nv_bfloat16* sAh = smb;
    __nv_bfloat16* sAl = smb + TILE_ELEMS;
    __nv_bfloat16* sWh = smb + 2 * TILE_ELEMS;
    __nv_bfloat16* sWl = smb + 3 * TILE_ELEMS;

    const int tid  = threadIdx.x;
    const int wid  = tid >> 5;
    const int lane = tid & 31;
    const int wm   = wid >> 1;          // 0..3
    const int wn   = wid & 1;           // 0..1
    const int grp  = lane >> 2;         // 0..7
    const int tq   = lane & 3;          // 0..3
    const int m0   = blockIdx.y * 128;
    const int n0   = blockIdx.x * 128;

    float d[2][8][4];
#pragma unroll
    for (int mt = 0; mt < 2; mt++)
#pragma unroll
        for (int nt = 0; nt < 8; nt++)
#pragma unroll
            for (int r = 0; r < 4; r++) d[mt][nt][r] = 0.f;

    for (int k0 = 0; k0 < K; k0 += 64) {
        __syncthreads();
        copy_tile(sAh, Ah + (size_t)m0 * K + k0, K, tid);
        copy_tile(sAl, Al + (size_t)m0 * K + k0, K, tid);
        copy_tile(sWh, Wh + (size_t)n0 * K + k0, K, tid);
        copy_tile(sWl, Wl + (size_t)n0 * K + k0, K, tid);
        __syncthreads();

#pragma unroll
        for (int kk = 0; kk < 64; kk += 16) {
            uint32_t ah[2][4], al[2][4];
#pragma unroll
            for (int mt = 0; mt < 2; mt++) {
                int r = wm * 32 + mt * 16 + grp;
                int c = kk + tq * 2;
                ah[mt][0] = ld_u32s(sAh + (r    ) * LDT + c    );
                ah[mt][1] = ld_u32s(sAh + (r + 8) * LDT + c    );
                ah[mt][2] = ld_u32s(sAh + (r    ) * LDT + c + 8);
                ah[mt][3] = ld_u32s(sAh + (r + 8) * LDT + c + 8);
                al[mt][0] = ld_u32s(sAl + (r    ) * LDT + c    );
                al[mt][1] = ld_u32s(sAl + (r + 8) * LDT + c    );
                al[mt][2] = ld_u32s(sAl + (r    ) * LDT + c + 8);
                al[mt][3] = ld_u32s(sAl + (r + 8) * LDT + c + 8);
            }
#pragma unroll
            for (int nt = 0; nt < 8; nt++) {
                int n = wn * 64 + nt * 8 + grp;
                int c = kk + tq * 2;
                uint32_t bh0 = ld_u32s(sWh + n * LDT + c);
                uint32_t bh1 = ld_u32s(sWh + n * LDT + c + 8);
                uint32_t bl0 = ld_u32s(sWl + n * LDT + c);
                uint32_t bl1 = ld_u32s(sWl + n * LDT + c + 8);
#pragma unroll
                for (int mt = 0; mt < 2; mt++) {
                    MMA16816(d[mt][nt], ah[mt], bh0, bh1);
                    MMA16816(d[mt][nt], al[mt], bh0, bh1);
                    MMA16816(d[mt][nt], ah[mt], bl0, bl1);
                }
            }
        }
    }

    // epilogue
#pragma unroll
    for (int mt = 0; mt < 2; mt++) {
        int r0 = m0 + wm * 32 + mt * 16 + grp;
#pragma unroll
        for (int nt = 0; nt < 8; nt++) {
            int cc = n0 + wn * 64 + nt * 8 + tq * 2;
            float b0 = bias[cc], b1 = bias[cc + 1];
            float2 o0 = make_float2(d[mt][nt][0] + b0, d[mt][nt][1] + b1);
            float2 o1 = make_float2(d[mt][nt][2] + b0, d[mt][nt][3] + b1);
            *(float2*)(C + (size_t)r0 * N + cc)       = o0;
            *(float2*)(C + (size_t)(r0 + 8) * N + cc) = o1;
        }
    }
}

// =================================================================
// Attention (fp32, online softmax + log-multiplicity), 3 CTAs/SM.
// =================================================================
#define ATTN_SMEM ((4 * 64 * 68 + 64) * 4)

__global__ __launch_bounds__(256, 3)
void attn_kernel(const float* __restrict__ Q, const float* __restrict__ Kt,
                 const float* __restrict__ V, const float* __restrict__ mult,
                 float* __restrict__ O)
{
    extern __shared__ float smf[];
    float (*Qs)[68] = (float(*)[68])(smf);
    float (*Ks)[68] = (float(*)[68])(smf + 64 * 68);
    float (*Vs)[68] = (float(*)[68])(smf + 2 * 64 * 68);
    float (*Ps)[68] = (float(*)[68])(smf + 3 * 64 * 68);
    float* Lm = smf + 4 * 64 * 68;

    const int tid = threadIdx.x;
    const int tx  = tid & 15;
    const int ty  = tid >> 4;
    const int qb  = blockIdx.x;
    const int h   = blockIdx.y;
    const int b   = blockIdx.z;

    const float* qp = Q  + (size_t)(b * NQS + qb * 64) * EMB + h * HD;
    const float* kp = Kt + (size_t)b * NKS * EMB + h * HD;
    const float* vp = V  + (size_t)b * NKS * EMB + h * HD;

#pragma unroll
    for (int i = 0; i < 4; i++) {
        int idx = tid + i * 256;
        int r = idx >> 4, c = (idx & 15) * 4;
        *(float4*)&Qs[r][c] = *(const float4*)(qp + (size_t)r * EMB + c);
    }

    float acc[4][4];
    float mrun[4], lrun[4];
#pragma unroll
    for (int i = 0; i < 4; i++) {
        mrun[i] = -3.4e38f;
        lrun[i] = 0.f;
#pragma unroll
        for (int j = 0; j < 4; j++) acc[i][j] = 0.f;
    }

    for (int k0 = 0; k0 < NKS; k0 += 64) {
        __syncthreads();
#pragma unroll
        for (int i = 0; i < 4; i++) {
            int idx = tid + i * 256;
            int r = idx >> 4, c = (idx & 15) * 4;
            *(float4*)&Ks[r][c] = *(const float4*)(kp + (size_t)(k0 + r) * EMB + c);
            *(float4*)&Vs[r][c] = *(const float4*)(vp + (size_t)(k0 + r) * EMB + c);
        }
        if (tid < 64) Lm[tid] = __logf(mult[b * NKS + k0 + tid]);
        __syncthreads();

        float s[4][4];
#pragma unroll
        for (int i = 0; i < 4; i++)
#pragma unroll
            for (int j = 0; j < 4; j++) s[i][j] = 0.f;

#pragma unroll 4
        for (int dd = 0; dd < 64; dd += 4) {
            float4 a[4], bb[4];
#pragma unroll
            for (int i = 0; i < 4; i++) a[i]  = *(const float4*)&Qs[ty * 4 + i][dd];
#pragma unroll
            for (int j = 0; j < 4; j++) bb[j] = *(const float4*)&Ks[tx * 4 + j][dd];
#pragma unroll
            for (int i = 0; i < 4; i++)
#pragma unroll
                for (int j = 0; j < 4; j++) {
                    s[i][j] = fmaf(a[i].x, bb[j].x, s[i][j]);
                    s[i][j] = fmaf(a[i].y, bb[j].y, s[i][j]);
                    s[i][j] = fmaf(a[i].z, bb[j].z, s[i][j]);
                    s[i][j] = fmaf(a[i].w, bb[j].w, s[i][j]);
                }
        }

#pragma unroll
        for (int i = 0; i < 4; i++) {
#pragma unroll
            for (int j = 0; j < 4; j++)
                s[i][j] = s[i][j] * 0.125f + Lm[tx * 4 + j];

            float mx = fmaxf(fmaxf(s[i][0], s[i][1]), fmaxf(s[i][2], s[i][3]));
#pragma unroll
            for (int o = 8; o >= 1; o >>= 1)
                mx = fmaxf(mx, __shfl_xor_sync(0xffffffffu, mx, o));
            float mnew = fmaxf(mrun[i], mx);
            float corr = __expf(mrun[i] - mnew);
            float rs = 0.f;
#pragma unroll
            for (int j = 0; j < 4; j++) {
                s[i][j] = __expf(s[i][j] - mnew);
                rs += s[i][j];
            }
#pragma unroll
            for (int o = 8; o >= 1; o >>= 1)
                rs += __shfl_xor_sync(0xffffffffu, rs, o);
            lrun[i] = lrun[i] * corr + rs;
            mrun[i] = mnew;
#pragma unroll
            for (int j = 0; j < 4; j++) acc[i][j] *= corr;
#pragma unroll
            for (int j = 0; j < 4; j++) Ps[ty * 4 + i][tx * 4 + j] = s[i][j];
        }
        __syncthreads();

#pragma unroll 8
        for (int c = 0; c < 64; c++) {
            float4 v4 = *(const float4*)&Vs[c][tx * 4];
#pragma unroll
            for (int i = 0; i < 4; i++) {
                float p = Ps[ty * 4 + i][c];
                acc[i][0] = fmaf(p, v4.x, acc[i][0]);
                acc[i][1] = fmaf(p, v4.y, acc[i][1]);
                acc[i][2] = fmaf(p, v4.z, acc[i][2]);
                acc[i][3] = fmaf(p, v4.w, acc[i][3]);
            }
        }
    }

    float* op = O + (size_t)(b * NQS + qb * 64) * EMB + h * HD;
#pragma unroll
    for (int i = 0; i < 4; i++) {
        float inv = 1.f / lrun[i];
#pragma unroll
        for (int j = 0; j < 4; j++)
            op[(size_t)(ty * 4 + i) * EMB + tx * 4 + j] = acc[i][j] * inv;
    }
}

// =================================================================
extern "C" void kernel_launch(void* const* d_in, const int* in_sizes, int n_in,
                              void* d_out, int out_size)
{
    const float* query = (const float*)d_in[0];
    const float* key_  = (const float*)d_in[1];
    const float* value = (const float*)d_in[2];
    const float* mult  = (const float*)d_in[3];
    const float* wq_w  = (const float*)d_in[4];
    const float* wq_b  = (const float*)d_in[5];
    const float* wk_w  = (const float*)d_in[6];
    const float* wk_b  = (const float*)d_in[7];
    const float* wv_w  = (const float*)d_in[8];
    const float* wv_b  = (const float*)d_in[9];
    const float* wo_w  = (const float*)d_in[10];
    const float* wo_b  = (const float*)d_in[11];
    float* out = (float*)d_out;

    float *q, *k, *v, *ao;
    __nv_bfloat16 *qh, *ql, *kh, *kl, *vh, *vl, *aoh, *aol, *wh, *wl;
    cudaGetSymbolAddress((void**)&q,   g_q);
    cudaGetSymbolAddress((void**)&k,   g_k);
    cudaGetSymbolAddress((void**)&v,   g_v);
    cudaGetSymbolAddress((void**)&ao,  g_ao);
    cudaGetSymbolAddress((void**)&qh,  g_qh);
    cudaGetSymbolAddress((void**)&ql,  g_ql);
    cudaGetSymbolAddress((void**)&kh,  g_kh);
    cudaGetSymbolAddress((void**)&kl,  g_kl);
    cudaGetSymbolAddress((void**)&vh,  g_vh);
    cudaGetSymbolAddress((void**)&vl,  g_vl);
    cudaGetSymbolAddress((void**)&aoh, g_aoh);
    cudaGetSymbolAddress((void**)&aol, g_aol);
    cudaGetSymbolAddress((void**)&wh,  g_wh);
    cudaGetSymbolAddress((void**)&wl,  g_wl);

    cudaFuncSetAttribute(attn_kernel,
                         cudaFuncAttributeMaxDynamicSharedMemorySize, ATTN_SMEM);
    cudaFuncSetAttribute(gemm_bf16x3,
                         cudaFuncAttributeMaxDynamicSharedMemorySize, G_SMEM);

    const size_t WSZ = (size_t)EMB * EMB;
    const int nq4 = BB * NQS * EMB / 4, nk4 = BB * NKS * EMB / 4, nw4 = (int)(WSZ / 4);

    split_kernel<<<(nq4 + 255) / 256, 256>>>(query, qh, ql, nq4);
    split_kernel<<<(nk4 + 255) / 256, 256>>>(key_,  kh, kl, nk4);
    split_kernel<<<(nk4 + 255) / 256, 256>>>(value, vh, vl, nk4);
    split_kernel<<<(nw4 + 255) / 256, 256>>>(wq_w, wh + 0 * WSZ, wl + 0 * WSZ, nw4);
    split_kernel<<<(nw4 + 255) / 256, 256>>>(wk_w, wh + 1 * WSZ, wl + 1 * WSZ, nw4);
    split_kernel<<<(nw4 + 255) / 256, 256>>>(wv_w, wh + 2 * WSZ, wl + 2 * WSZ, nw4);
    split_kernel<<<(nw4 + 255) / 256, 256>>>(wo_w, wh + 3 * WSZ, wl + 3 * WSZ, nw4);

    dim3 gq(EMB / 128, (BB * NQS) / 128);   // (8, 32)
    dim3 gk(EMB / 128, (BB * NKS) / 128);   // (8, 64)

    gemm_bf16x3<<<gq, 256, G_SMEM>>>(qh, ql, wh + 0 * WSZ, wl + 0 * WSZ, wq_b, q,
                                     BB * NQS, EMB, EMB);
    gemm_bf16x3<<<gk, 256, G_SMEM>>>(kh, kl, wh + 1 * WSZ, wl + 1 * WSZ, wk_b, k,
                                     BB * NKS, EMB, EMB);
    gemm_bf16x3<<<gk, 256, G_SMEM>>>(vh, vl, wh + 2 * WSZ, wl + 2 * WSZ, wv_b, v,
                                     BB * NKS, EMB, EMB);

    dim3 ga(NQS / 64, NH, BB);              // (16, 16, 4)
    attn_kernel<<<ga, 256, ATTN_SMEM>>>(q, k, v, mult, ao);

    split_kernel<<<(nq4 + 255) / 256, 256>>>(ao, aoh, aol, nq4);
    gemm_bf16x3<<<gq, 256, G_SMEM>>>(aoh, aol, wh + 3 * WSZ, wl + 3 * WSZ, wo_b, out,
                                     BB * NQS, EMB, EMB);
}

// round 5
// speedup vs baseline: 2.6763x; 2.0490x over previous
#include <cuda_runtime.h>
#include <cuda_bf16.h>
#include <cstdint>

#define EMB 1024
#define BB  4
#define NQS 1024
#define NKS 2048
#define NH  16
#define HD  64

// ---------------- scratch (no allocations allowed) ----------------
__device__ __nv_bfloat16 g_qh [(size_t)BB * NQS * EMB];   // split input query
__device__ __nv_bfloat16 g_ql [(size_t)BB * NQS * EMB];
__device__ __nv_bfloat16 g_kh [(size_t)BB * NKS * EMB];   // split input key
__device__ __nv_bfloat16 g_kl [(size_t)BB * NKS * EMB];
__device__ __nv_bfloat16 g_vh [(size_t)BB * NKS * EMB];   // split input value
__device__ __nv_bfloat16 g_vl [(size_t)BB * NKS * EMB];
__device__ __nv_bfloat16 g_wh [4][(size_t)EMB * EMB];     // weights hi (q,k,v,o)
__device__ __nv_bfloat16 g_wl [4][(size_t)EMB * EMB];     // weights lo
__device__ __nv_bfloat16 g_pqh[(size_t)BB * NQS * EMB];   // projected q hi/lo
__device__ __nv_bfloat16 g_pql[(size_t)BB * NQS * EMB];
__device__ __nv_bfloat16 g_pkh[(size_t)BB * NKS * EMB];   // projected k hi/lo
__device__ __nv_bfloat16 g_pkl[(size_t)BB * NKS * EMB];
__device__ __nv_bfloat16 g_pvh[(size_t)BB * NKS * EMB];   // projected v hi/lo
__device__ __nv_bfloat16 g_pvl[(size_t)BB * NKS * EMB];
__device__ __nv_bfloat16 g_aoh[(size_t)BB * NQS * EMB];   // attention out hi/lo
__device__ __nv_bfloat16 g_aol[(size_t)BB * NQS * EMB];

// ================= helpers =================
__device__ __forceinline__ uint32_t smem_u32(const void* p) {
    uint32_t a;
    asm("{ .reg .u64 t; cvta.to.shared.u64 t, %1; cvt.u32.u64 %0, t; }" : "=r"(a) : "l"(p));
    return a;
}
__device__ __forceinline__ uint32_t ld_u32s(const __nv_bfloat16* p) {
    return *(const uint32_t*)p;
}
// pack two fp32 -> bf16x2 (lo = first arg, hi = second)
__device__ __forceinline__ uint32_t pack_bf(float lo, float hi) {
    uint32_t r;
    asm("cvt.rn.bf16x2.f32 %0, %1, %2;" : "=r"(r) : "f"(hi), "f"(lo));
    return r;
}
__device__ __forceinline__ float bfx2_lo(uint32_t v) { return __uint_as_float(v << 16); }
__device__ __forceinline__ float bfx2_hi(uint32_t v) { return __uint_as_float(v & 0xffff0000u); }

#define MMA16816(d, a, b0, b1)                                            \
    asm volatile("mma.sync.aligned.m16n8k16.row.col.f32.bf16.bf16.f32 "   \
                 "{%0,%1,%2,%3}, {%4,%5,%6,%7}, {%8,%9}, {%0,%1,%2,%3};"  \
                 : "+f"((d)[0]), "+f"((d)[1]), "+f"((d)[2]), "+f"((d)[3]) \
                 : "r"((a)[0]), "r"((a)[1]), "r"((a)[2]), "r"((a)[3]),    \
                   "r"(b0), "r"(b1))

#define LDSM_X4_T(r0, r1, r2, r3, addr)                                        \
    asm volatile("ldmatrix.sync.aligned.m8n8.x4.trans.shared.b16 "             \
                 "{%0,%1,%2,%3}, [%4];"                                        \
                 : "=r"(r0), "=r"(r1), "=r"(r2), "=r"(r3) : "r"(addr))

// ============== split fp32 -> bf16 hi + bf16 lo ==================
__global__ __launch_bounds__(256)
void split_kernel(const float* __restrict__ x, __nv_bfloat16* __restrict__ hi,
                  __nv_bfloat16* __restrict__ lo, int n4)
{
    int i = blockIdx.x * blockDim.x + threadIdx.x;
    if (i >= n4) return;
    float4 v = ((const float4*)x)[i];
    uint32_t h0 = pack_bf(v.x, v.y), h1 = pack_bf(v.z, v.w);
    uint32_t l0 = pack_bf(v.x - bfx2_lo(h0), v.y - bfx2_hi(h0));
    uint32_t l1 = pack_bf(v.z - bfx2_lo(h1), v.w - bfx2_hi(h1));
    ((uint32_t*)hi)[2 * i] = h0; ((uint32_t*)hi)[2 * i + 1] = h1;
    ((uint32_t*)lo)[2 * i] = l0; ((uint32_t*)lo)[2 * i + 1] = l1;
}

// ============== bf16x3 mma.sync GEMM: C = A @ W^T + bias =========
// mode bit0: write fp32 C; bit1: write bf16 hi/lo outputs.
#define LDT 72
#define TILE_ELEMS (128 * LDT)
#define G_SMEM (4 * TILE_ELEMS * 2)

__device__ __forceinline__ void copy_tile(__nv_bfloat16* dst,
                                          const __nv_bfloat16* src,
                                          int ldk, int tid)
{
#pragma unroll
    for (int i = 0; i < 4; i++) {
        int idx = tid + i * 256;
        int r = idx >> 3, c8 = idx & 7;
        float4 v = *(const float4*)(src + (size_t)r * ldk + c8 * 8);
        *(float4*)(dst + r * LDT + c8 * 8) = v;
    }
}

__global__ __launch_bounds__(256)
void gemm_bf16x3(const __nv_bfloat16* __restrict__ Ah, const __nv_bfloat16* __restrict__ Al,
                 const __nv_bfloat16* __restrict__ Wh, const __nv_bfloat16* __restrict__ Wl,
                 const float* __restrict__ bias, float* __restrict__ C,
                 __nv_bfloat16* __restrict__ Chi, __nv_bfloat16* __restrict__ Clo,
                 int M, int N, int K, int mode)
{
    extern __shared__ __nv_bfloat16 smb[];
    __nv_bfloat16* sAh = smb;
    __nv_bfloat16* sAl = smb + TILE_ELEMS;
    __nv_bfloat16* sWh = smb + 2 * TILE_ELEMS;
    __nv_bfloat16* sWl = smb + 3 * TILE_ELEMS;

    const int tid  = threadIdx.x;
    const int wid  = tid >> 5;
    const int lane = tid & 31;
    const int wm   = wid >> 1;
    const int wn   = wid & 1;
    const int grp  = lane >> 2;
    const int tq   = lane & 3;
    const int m0   = blockIdx.y * 128;
    const int n0   = blockIdx.x * 128;

    float d[2][8][4];
#pragma unroll
    for (int mt = 0; mt < 2; mt++)
#pragma unroll
        for (int nt = 0; nt < 8; nt++)
#pragma unroll
            for (int r = 0; r < 4; r++) d[mt][nt][r] = 0.f;

    for (int k0 = 0; k0 < K; k0 += 64) {
        __syncthreads();
        copy_tile(sAh, Ah + (size_t)m0 * K + k0, K, tid);
        copy_tile(sAl, Al + (size_t)m0 * K + k0, K, tid);
        copy_tile(sWh, Wh + (size_t)n0 * K + k0, K, tid);
        copy_tile(sWl, Wl + (size_t)n0 * K + k0, K, tid);
        __syncthreads();

#pragma unroll
        for (int kk = 0; kk < 64; kk += 16) {
            uint32_t ah[2][4], al[2][4];
#pragma unroll
            for (int mt = 0; mt < 2; mt++) {
                int r = wm * 32 + mt * 16 + grp;
                int c = kk + tq * 2;
                ah[mt][0] = ld_u32s(sAh + (r    ) * LDT + c    );
                ah[mt][1] = ld_u32s(sAh + (r + 8) * LDT + c    );
                ah[mt][2] = ld_u32s(sAh + (r    ) * LDT + c + 8);
                ah[mt][3] = ld_u32s(sAh + (r + 8) * LDT + c + 8);
                al[mt][0] = ld_u32s(sAl + (r    ) * LDT + c    );
                al[mt][1] = ld_u32s(sAl + (r + 8) * LDT + c    );
                al[mt][2] = ld_u32s(sAl + (r    ) * LDT + c + 8);
                al[mt][3] = ld_u32s(sAl + (r + 8) * LDT + c + 8);
            }
#pragma unroll
            for (int nt = 0; nt < 8; nt++) {
                int n = wn * 64 + nt * 8 + grp;
                int c = kk + tq * 2;
                uint32_t bh0 = ld_u32s(sWh + n * LDT + c);
                uint32_t bh1 = ld_u32s(sWh + n * LDT + c + 8);
                uint32_t bl0 = ld_u32s(sWl + n * LDT + c);
                uint32_t bl1 = ld_u32s(sWl + n * LDT + c + 8);
#pragma unroll
                for (int mt = 0; mt < 2; mt++) {
                    MMA16816(d[mt][nt], ah[mt], bh0, bh1);
                    MMA16816(d[mt][nt], al[mt], bh0, bh1);
                    MMA16816(d[mt][nt], ah[mt], bl0, bl1);
                }
            }
        }
    }

#pragma unroll
    for (int mt = 0; mt < 2; mt++) {
        int r0 = m0 + wm * 32 + mt * 16 + grp;
#pragma unroll
        for (int nt = 0; nt < 8; nt++) {
            int cc = n0 + wn * 64 + nt * 8 + tq * 2;
            float b0 = bias[cc], b1 = bias[cc + 1];
            float v00 = d[mt][nt][0] + b0, v01 = d[mt][nt][1] + b1;
            float v10 = d[mt][nt][2] + b0, v11 = d[mt][nt][3] + b1;
            if (mode & 1) {
                *(float2*)(C + (size_t)r0 * N + cc)       = make_float2(v00, v01);
                *(float2*)(C + (size_t)(r0 + 8) * N + cc) = make_float2(v10, v11);
            }
            if (mode & 2) {
                uint32_t h0 = pack_bf(v00, v01), h1 = pack_bf(v10, v11);
                uint32_t l0 = pack_bf(v00 - bfx2_lo(h0), v01 - bfx2_hi(h0));
                uint32_t l1 = pack_bf(v10 - bfx2_lo(h1), v11 - bfx2_hi(h1));
                *(uint32_t*)(Chi + (size_t)r0 * N + cc)       = h0;
                *(uint32_t*)(Chi + (size_t)(r0 + 8) * N + cc) = h1;
                *(uint32_t*)(Clo + (size_t)r0 * N + cc)       = l0;
                *(uint32_t*)(Clo + (size_t)(r0 + 8) * N + cc) = l1;
            }
        }
    }
}

// =================================================================
// Tensor-core attention: q-tile 64, 4 warps, bf16x3 everywhere.
// S-frag D layout == P-frag A layout (no shuffles). V via ldmatrix.trans.
// =================================================================
#define ALDT 72
#define ATILE (64 * ALDT)                        // elems per 64x64 tile
#define ATTN_SMEM (6 * ATILE * 2 + 64 * 4)       // 6 bf16 tiles + Lm[64] fp32

__global__ __launch_bounds__(128)
void attn_mma(const __nv_bfloat16* __restrict__ Qh, const __nv_bfloat16* __restrict__ Ql,
              const __nv_bfloat16* __restrict__ Kh, const __nv_bfloat16* __restrict__ Kl,
              const __nv_bfloat16* __restrict__ Vh, const __nv_bfloat16* __restrict__ Vl,
              const float* __restrict__ mult,
              __nv_bfloat16* __restrict__ Ohi, __nv_bfloat16* __restrict__ Olo)
{
    extern __shared__ __nv_bfloat16 smb[];
    __nv_bfloat16* sQh = smb;
    __nv_bfloat16* sQl = smb + ATILE;
    __nv_bfloat16* sKh = smb + 2 * ATILE;
    __nv_bfloat16* sKl = smb + 3 * ATILE;
    __nv_bfloat16* sVh = smb + 4 * ATILE;
    __nv_bfloat16* sVl = smb + 5 * ATILE;
    float* Lm = (float*)(smb + 6 * ATILE);

    const int tid  = threadIdx.x;
    const int wid  = tid >> 5;
    const int lane = tid & 31;
    const int grp  = lane >> 2;
    const int tq   = lane & 3;
    const int qb   = blockIdx.x;
    const int h    = blockIdx.y;
    const int b    = blockIdx.z;

    const size_t qoff  = ((size_t)(b * NQS + qb * 64)) * EMB + h * HD;
    const size_t kbase = ((size_t)b * NKS) * EMB + h * HD;

    // stage Q tile (64x64)
#pragma unroll
    for (int i = 0; i < 4; i++) {
        int idx = tid + i * 128;
        int r = idx >> 3, c8 = idx & 7;
        *(float4*)(sQh + r * ALDT + c8 * 8) = *(const float4*)(Qh + qoff + (size_t)r * EMB + c8 * 8);
        *(float4*)(sQl + r * ALDT + c8 * 8) = *(const float4*)(Ql + qoff + (size_t)r * EMB + c8 * 8);
    }
    __syncthreads();

    // Q fragments held in registers for whole kernel
    uint32_t aqh[4][4], aql[4][4];
#pragma unroll
    for (int ks = 0; ks < 4; ks++) {
        int r = wid * 16 + grp;
        int c = ks * 16 + tq * 2;
        aqh[ks][0] = ld_u32s(sQh + (r    ) * ALDT + c    );
        aqh[ks][1] = ld_u32s(sQh + (r + 8) * ALDT + c    );
        aqh[ks][2] = ld_u32s(sQh + (r    ) * ALDT + c + 8);
        aqh[ks][3] = ld_u32s(sQh + (r + 8) * ALDT + c + 8);
        aql[ks][0] = ld_u32s(sQl + (r    ) * ALDT + c    );
        aql[ks][1] = ld_u32s(sQl + (r + 8) * ALDT + c    );
        aql[ks][2] = ld_u32s(sQl + (r    ) * ALDT + c + 8);
        aql[ks][3] = ld_u32s(sQl + (r + 8) * ALDT + c + 8);
    }

    float dO[8][4];
#pragma unroll
    for (int nt = 0; nt < 8; nt++)
#pragma unroll
        for (int r = 0; r < 4; r++) dO[nt][r] = 0.f;
    float mrun0 = -3.4e38f, mrun1 = -3.4e38f, lrun0 = 0.f, lrun1 = 0.f;

    const uint32_t svh_base = smem_u32(sVh);
    const uint32_t svl_base = smem_u32(sVl);

    for (int k0 = 0; k0 < NKS; k0 += 64) {
        __syncthreads();
#pragma unroll
        for (int i = 0; i < 4; i++) {
            int idx = tid + i * 128;
            int r = idx >> 3, c8 = idx & 7;
            size_t src = kbase + (size_t)(k0 + r) * EMB + c8 * 8;
            *(float4*)(sKh + r * ALDT + c8 * 8) = *(const float4*)(Kh + src);
            *(float4*)(sKl + r * ALDT + c8 * 8) = *(const float4*)(Kl + src);
            *(float4*)(sVh + r * ALDT + c8 * 8) = *(const float4*)(Vh + src);
            *(float4*)(sVl + r * ALDT + c8 * 8) = *(const float4*)(Vl + src);
        }
        if (tid < 64) Lm[tid] = __logf(mult[b * NKS + k0 + tid]);
        __syncthreads();

        // S = Q @ K^T (bf16x3)
        float dS[8][4];
#pragma unroll
        for (int nt = 0; nt < 8; nt++) {
#pragma unroll
            for (int r = 0; r < 4; r++) dS[nt][r] = 0.f;
#pragma unroll
            for (int ks = 0; ks < 4; ks++) {
                int n = nt * 8 + grp;
                int c = ks * 16 + tq * 2;
                uint32_t bh0 = ld_u32s(sKh + n * ALDT + c);
                uint32_t bh1 = ld_u32s(sKh + n * ALDT + c + 8);
                uint32_t bl0 = ld_u32s(sKl + n * ALDT + c);
                uint32_t bl1 = ld_u32s(sKl + n * ALDT + c + 8);
                MMA16816(dS[nt], aqh[ks], bh0, bh1);
                MMA16816(dS[nt], aql[ks], bh0, bh1);
                MMA16816(dS[nt], aqh[ks], bl0, bl1);
            }
        }

        // logits + online softmax on fragments (rows grp / grp+8)
        float mx0 = -3.4e38f, mx1 = -3.4e38f;
#pragma unroll
        for (int nt = 0; nt < 8; nt++) {
            float lm0 = Lm[nt * 8 + tq * 2], lm1 = Lm[nt * 8 + tq * 2 + 1];
            dS[nt][0] = dS[nt][0] * 0.125f + lm0;
            dS[nt][1] = dS[nt][1] * 0.125f + lm1;
            dS[nt][2] = dS[nt][2] * 0.125f + lm0;
            dS[nt][3] = dS[nt][3] * 0.125f + lm1;
            mx0 = fmaxf(mx0, fmaxf(dS[nt][0], dS[nt][1]));
            mx1 = fmaxf(mx1, fmaxf(dS[nt][2], dS[nt][3]));
        }
        mx0 = fmaxf(mx0, __shfl_xor_sync(0xffffffffu, mx0, 1));
        mx0 = fmaxf(mx0, __shfl_xor_sync(0xffffffffu, mx0, 2));
        mx1 = fmaxf(mx1, __shfl_xor_sync(0xffffffffu, mx1, 1));
        mx1 = fmaxf(mx1, __shfl_xor_sync(0xffffffffu, mx1, 2));
        float mnew0 = fmaxf(mrun0, mx0), mnew1 = fmaxf(mrun1, mx1);
        float corr0 = __expf(mrun0 - mnew0), corr1 = __expf(mrun1 - mnew1);
        float rs0 = 0.f, rs1 = 0.f;
#pragma unroll
        for (int nt = 0; nt < 8; nt++) {
            dS[nt][0] = __expf(dS[nt][0] - mnew0); rs0 += dS[nt][0];
            dS[nt][1] = __expf(dS[nt][1] - mnew0); rs0 += dS[nt][1];
            dS[nt][2] = __expf(dS[nt][2] - mnew1); rs1 += dS[nt][2];
            dS[nt][3] = __expf(dS[nt][3] - mnew1); rs1 += dS[nt][3];
        }
        rs0 += __shfl_xor_sync(0xffffffffu, rs0, 1);
        rs0 += __shfl_xor_sync(0xffffffffu, rs0, 2);
        rs1 += __shfl_xor_sync(0xffffffffu, rs1, 1);
        rs1 += __shfl_xor_sync(0xffffffffu, rs1, 2);
        lrun0 = lrun0 * corr0 + rs0; mrun0 = mnew0;
        lrun1 = lrun1 * corr1 + rs1; mrun1 = mnew1;
#pragma unroll
        for (int nt = 0; nt < 8; nt++) {
            dO[nt][0] *= corr0; dO[nt][1] *= corr0;
            dO[nt][2] *= corr1; dO[nt][3] *= corr1;
        }

        // O += P @ V  (P hi/lo packed straight from dS fragments)
#pragma unroll
        for (int kb = 0; kb < 4; kb++) {
            uint32_t ph[4], pl[4];
            ph[0] = pack_bf(dS[2 * kb][0],     dS[2 * kb][1]);
            ph[1] = pack_bf(dS[2 * kb][2],     dS[2 * kb][3]);
            ph[2] = pack_bf(dS[2 * kb + 1][0], dS[2 * kb + 1][1]);
            ph[3] = pack_bf(dS[2 * kb + 1][2], dS[2 * kb + 1][3]);
            pl[0] = pack_bf(dS[2 * kb][0] - bfx2_lo(ph[0]),     dS[2 * kb][1] - bfx2_hi(ph[0]));
            pl[1] = pack_bf(dS[2 * kb][2] - bfx2_lo(ph[1]),     dS[2 * kb][3] - bfx2_hi(ph[1]));
            pl[2] = pack_bf(dS[2 * kb + 1][0] - bfx2_lo(ph[2]), dS[2 * kb + 1][1] - bfx2_hi(ph[2]));
            pl[3] = pack_bf(dS[2 * kb + 1][2] - bfx2_lo(ph[3]), dS[2 * kb + 1][3] - bfx2_hi(ph[3]));

#pragma unroll
            for (int np = 0; np < 4; np++) {
                int krow = kb * 16 + (lane & 15);
                int ncol = np * 16 + ((lane >> 4) << 3);
                uint32_t off = (uint32_t)(krow * ALDT + ncol) * 2;
                uint32_t vh[4], vl[4];
                LDSM_X4_T(vh[0], vh[1], vh[2], vh[3], svh_base + off);
                LDSM_X4_T(vl[0], vl[1], vl[2], vl[3], svl_base + off);
                MMA16816(dO[2 * np],     ph, vh[0], vh[1]);
                MMA16816(dO[2 * np],     pl, vh[0], vh[1]);
                MMA16816(dO[2 * np],     ph, vl[0], vl[1]);
                MMA16816(dO[2 * np + 1], ph, vh[2], vh[3]);
                MMA16816(dO[2 * np + 1], pl, vh[2], vh[3]);
                MMA16816(dO[2 * np + 1], ph, vl[2], vl[3]);
            }
        }
    }

    // epilogue: normalize, emit bf16 hi/lo directly
    float inv0 = 1.f / lrun0, inv1 = 1.f / lrun1;
    int gr0 = qb * 64 + wid * 16 + grp;
#pragma unroll
    for (int nt = 0; nt < 8; nt++) {
        int col = h * HD + nt * 8 + tq * 2;
        float o00 = dO[nt][0] * inv0, o01 = dO[nt][1] * inv0;
        float o10 = dO[nt][2] * inv1, o11 = dO[nt][3] * inv1;
        uint32_t h0 = pack_bf(o00, o01), h1 = pack_bf(o10, o11);
        uint32_t l0 = pack_bf(o00 - bfx2_lo(h0), o01 - bfx2_hi(h0));
        uint32_t l1 = pack_bf(o10 - bfx2_lo(h1), o11 - bfx2_hi(h1));
        size_t p0 = ((size_t)(b * NQS + gr0)) * EMB + col;
        size_t p1 = ((size_t)(b * NQS + gr0 + 8)) * EMB + col;
        *(uint32_t*)(Ohi + p0) = h0; *(uint32_t*)(Ohi + p1) = h1;
        *(uint32_t*)(Olo + p0) = l0; *(uint32_t*)(Olo + p1) = l1;
    }
}

// =================================================================
extern "C" void kernel_launch(void* const* d_in, const int* in_sizes, int n_in,
                              void* d_out, int out_size)
{
    const float* query = (const float*)d_in[0];
    const float* key_  = (const float*)d_in[1];
    const float* value = (const float*)d_in[2];
    const float* mult  = (const float*)d_in[3];
    const float* wq_w  = (const float*)d_in[4];
    const float* wq_b  = (const float*)d_in[5];
    const float* wk_w  = (const float*)d_in[6];
    const float* wk_b  = (const float*)d_in[7];
    const float* wv_w  = (const float*)d_in[8];
    const float* wv_b  = (const float*)d_in[9];
    const float* wo_w  = (const float*)d_in[10];
    const float* wo_b  = (const float*)d_in[11];
    float* out = (float*)d_out;

    __nv_bfloat16 *qh, *ql, *kh, *kl, *vh, *vl, *wh, *wl;
    __nv_bfloat16 *pqh, *pql, *pkh, *pkl, *pvh, *pvl, *aoh, *aol;
    cudaGetSymbolAddress((void**)&qh,  g_qh);
    cudaGetSymbolAddress((void**)&ql,  g_ql);
    cudaGetSymbolAddress((void**)&kh,  g_kh);
    cudaGetSymbolAddress((void**)&kl,  g_kl);
    cudaGetSymbolAddress((void**)&vh,  g_vh);
    cudaGetSymbolAddress((void**)&vl,  g_vl);
    cudaGetSymbolAddress((void**)&wh,  g_wh);
    cudaGetSymbolAddress((void**)&wl,  g_wl);
    cudaGetSymbolAddress((void**)&pqh, g_pqh);
    cudaGetSymbolAddress((void**)&pql, g_pql);
    cudaGetSymbolAddress((void**)&pkh, g_pkh);
    cudaGetSymbolAddress((void**)&pkl, g_pkl);
    cudaGetSymbolAddress((void**)&pvh, g_pvh);
    cudaGetSymbolAddress((void**)&pvl, g_pvl);
    cudaGetSymbolAddress((void**)&aoh, g_aoh);
    cudaGetSymbolAddress((void**)&aol, g_aol);

    cudaFuncSetAttribute(gemm_bf16x3,
                         cudaFuncAttributeMaxDynamicSharedMemorySize, G_SMEM);
    cudaFuncSetAttribute(attn_mma,
                         cudaFuncAttributeMaxDynamicSharedMemorySize, ATTN_SMEM);

    const size_t WSZ = (size_t)EMB * EMB;
    const int nq4 = BB * NQS * EMB / 4, nk4 = BB * NKS * EMB / 4, nw4 = (int)(WSZ / 4);

    split_kernel<<<(nq4 + 255) / 256, 256>>>(query, qh, ql, nq4);
    split_kernel<<<(nk4 + 255) / 256, 256>>>(key_,  kh, kl, nk4);
    split_kernel<<<(nk4 + 255) / 256, 256>>>(value, vh, vl, nk4);
    split_kernel<<<(nw4 + 255) / 256, 256>>>(wq_w, wh + 0 * WSZ, wl + 0 * WSZ, nw4);
    split_kernel<<<(nw4 + 255) / 256, 256>>>(wk_w, wh + 1 * WSZ, wl + 1 * WSZ, nw4);
    split_kernel<<<(nw4 + 255) / 256, 256>>>(wv_w, wh + 2 * WSZ, wl + 2 * WSZ, nw4);
    split_kernel<<<(nw4 + 255) / 256, 256>>>(wo_w, wh + 3 * WSZ, wl + 3 * WSZ, nw4);

    dim3 gq(EMB / 128, (BB * NQS) / 128);   // (8, 32)
    dim3 gk(EMB / 128, (BB * NKS) / 128);   // (8, 64)

    // projections: emit bf16 hi/lo directly (mode=2)
    gemm_bf16x3<<<gq, 256, G_SMEM>>>(qh, ql, wh + 0 * WSZ, wl + 0 * WSZ, wq_b,
                                     out, pqh, pql, BB * NQS, EMB, EMB, 2);
    gemm_bf16x3<<<gk, 256, G_SMEM>>>(kh, kl, wh + 1 * WSZ, wl + 1 * WSZ, wk_b,
                                     out, pkh, pkl, BB * NKS, EMB, EMB, 2);
    gemm_bf16x3<<<gk, 256, G_SMEM>>>(vh, vl, wh + 2 * WSZ, wl + 2 * WSZ, wv_b,
                                     out, pvh, pvl, BB * NKS, EMB, EMB, 2);

    dim3 ga(NQS / 64, NH, BB);              // (16, 16, 4)
    attn_mma<<<ga, 128, ATTN_SMEM>>>(pqh, pql, pkh, pkl, pvh, pvl, mult, aoh, aol);

    // output projection: fp32 out (mode=1)
    gemm_bf16x3<<<gq, 256, G_SMEM>>>(aoh, aol, wh + 3 * WSZ, wl + 3 * WSZ, wo_b,
                                     out, aoh, aol, BB * NQS, EMB, EMB, 1);
}

// round 6
// speedup vs baseline: 3.0586x; 1.1429x over previous
#include <cuda_runtime.h>
#include <cuda_bf16.h>
#include <cstdint>

#define EMB 1024
#define BB  4
#define NQS 1024
#define NKS 2048
#define NH  16
#define HD  64

// ---------------- scratch (no allocations allowed) ----------------
__device__ __nv_bfloat16 g_qh [(size_t)BB * NQS * EMB];
__device__ __nv_bfloat16 g_ql [(size_t)BB * NQS * EMB];
__device__ __nv_bfloat16 g_kh [(size_t)BB * NKS * EMB];
__device__ __nv_bfloat16 g_kl [(size_t)BB * NKS * EMB];
__device__ __nv_bfloat16 g_vh [(size_t)BB * NKS * EMB];
__device__ __nv_bfloat16 g_vl [(size_t)BB * NKS * EMB];
__device__ __nv_bfloat16 g_wh [4][(size_t)EMB * EMB];
__device__ __nv_bfloat16 g_wl [4][(size_t)EMB * EMB];
__device__ __nv_bfloat16 g_pqh[(size_t)BB * NQS * EMB];
__device__ __nv_bfloat16 g_pql[(size_t)BB * NQS * EMB];
__device__ __nv_bfloat16 g_pkh[(size_t)BB * NKS * EMB];
__device__ __nv_bfloat16 g_pkl[(size_t)BB * NKS * EMB];
__device__ __nv_bfloat16 g_pvh[(size_t)BB * NKS * EMB];
__device__ __nv_bfloat16 g_pvl[(size_t)BB * NKS * EMB];
__device__ __nv_bfloat16 g_aoh[(size_t)BB * NQS * EMB];
__device__ __nv_bfloat16 g_aol[(size_t)BB * NQS * EMB];

// ================= helpers =================
__device__ __forceinline__ uint32_t smem_u32(const void* p) {
    uint32_t a;
    asm("{ .reg .u64 t; cvta.to.shared.u64 t, %1; cvt.u32.u64 %0, t; }" : "=r"(a) : "l"(p));
    return a;
}
__device__ __forceinline__ uint32_t ld_u32s(const __nv_bfloat16* p) {
    return *(const uint32_t*)p;
}
__device__ __forceinline__ uint32_t pack_bf(float lo, float hi) {
    uint32_t r;
    asm("cvt.rn.bf16x2.f32 %0, %1, %2;" : "=r"(r) : "f"(hi), "f"(lo));
    return r;
}
__device__ __forceinline__ float bfx2_lo(uint32_t v) { return __uint_as_float(v << 16); }
__device__ __forceinline__ float bfx2_hi(uint32_t v) { return __uint_as_float(v & 0xffff0000u); }

#define MMA16816(d, a, b0, b1)                                            \
    asm volatile("mma.sync.aligned.m16n8k16.row.col.f32.bf16.bf16.f32 "   \
                 "{%0,%1,%2,%3}, {%4,%5,%6,%7}, {%8,%9}, {%0,%1,%2,%3};"  \
                 : "+f"((d)[0]), "+f"((d)[1]), "+f"((d)[2]), "+f"((d)[3]) \
                 : "r"((a)[0]), "r"((a)[1]), "r"((a)[2]), "r"((a)[3]),    \
                   "r"(b0), "r"(b1))

#define LDSM_X4(r0, r1, r2, r3, addr)                                          \
    asm volatile("ldmatrix.sync.aligned.m8n8.x4.shared.b16 {%0,%1,%2,%3}, [%4];" \
                 : "=r"(r0), "=r"(r1), "=r"(r2), "=r"(r3) : "r"(addr))

#define LDSM_X4_T(r0, r1, r2, r3, addr)                                        \
    asm volatile("ldmatrix.sync.aligned.m8n8.x4.trans.shared.b16 "             \
                 "{%0,%1,%2,%3}, [%4];"                                        \
                 : "=r"(r0), "=r"(r1), "=r"(r2), "=r"(r3) : "r"(addr))

__device__ __forceinline__ void cp16(uint32_t dst, const void* src) {
    asm volatile("cp.async.cg.shared.global [%0], [%1], 16;" :: "r"(dst), "l"(src));
}
#define CP_COMMIT()  asm volatile("cp.async.commit_group;" ::: "memory")
#define CP_WAIT(n)   asm volatile("cp.async.wait_group %0;" :: "n"(n) : "memory")

// ============== split fp32 -> bf16 hi + bf16 lo ==================
__global__ __launch_bounds__(256)
void split_kernel(const float* __restrict__ x, __nv_bfloat16* __restrict__ hi,
                  __nv_bfloat16* __restrict__ lo, int n4)
{
    int i = blockIdx.x * blockDim.x + threadIdx.x;
    if (i >= n4) return;
    float4 v = ((const float4*)x)[i];
    uint32_t h0 = pack_bf(v.x, v.y), h1 = pack_bf(v.z, v.w);
    uint32_t l0 = pack_bf(v.x - bfx2_lo(h0), v.y - bfx2_hi(h0));
    uint32_t l1 = pack_bf(v.z - bfx2_lo(h1), v.w - bfx2_hi(h1));
    ((uint32_t*)hi)[2 * i] = h0; ((uint32_t*)hi)[2 * i + 1] = h1;
    ((uint32_t*)lo)[2 * i] = l0; ((uint32_t*)lo)[2 * i + 1] = l1;
}

// ============== bf16x3 mma.sync GEMM, cp.async 2-stage ===========
// 128x128 CTA tile, K-chunk 32, 8 warps (4m x 2n), warp tile 32x64.
// Per stage: Ah, Al, Wh, Wl tiles of 128 x 32 bf16, rows padded to 40.
#define LDT2 40
#define GT_ELEMS (128 * LDT2)                 // 5120 elems / tile
#define STAGE_ELEMS (4 * GT_ELEMS)            // 20480
#define G_SMEM2 (2 * STAGE_ELEMS * 2)         // 81920 B

__device__ __forceinline__ void stage_loads(uint32_t sbase,
                                            const __nv_bfloat16* Ah, const __nv_bfloat16* Al,
                                            const __nv_bfloat16* Wh, const __nv_bfloat16* Wl,
                                            size_t aoff, size_t woff, int K, int tid)
{
    const __nv_bfloat16* srcs[4] = {Ah + aoff, Al + aoff, Wh + woff, Wl + woff};
#pragma unroll
    for (int t = 0; t < 4; t++) {
        uint32_t tb = sbase + t * (GT_ELEMS * 2);
        const __nv_bfloat16* s = srcs[t];
#pragma unroll
        for (int j = 0; j < 2; j++) {
            int idx = tid + j * 256;            // 0..511
            int r = idx >> 2, c16 = idx & 3;    // 128 rows x 4 16B-chunks
            cp16(tb + r * (LDT2 * 2) + c16 * 16,
                 s + (size_t)r * K + c16 * 8);
        }
    }
}

__global__ __launch_bounds__(256)
void gemm_bf16x3(const __nv_bfloat16* __restrict__ Ah, const __nv_bfloat16* __restrict__ Al,
                 const __nv_bfloat16* __restrict__ Wh, const __nv_bfloat16* __restrict__ Wl,
                 const float* __restrict__ bias, float* __restrict__ C,
                 __nv_bfloat16* __restrict__ Chi, __nv_bfloat16* __restrict__ Clo,
                 int M, int N, int K, int mode)
{
    extern __shared__ __nv_bfloat16 smb[];
    const uint32_t sb = smem_u32(smb);

    const int tid  = threadIdx.x;
    const int wid  = tid >> 5;
    const int lane = tid & 31;
    const int grp  = lane >> 2;
    const int tq   = lane & 3;
    const int wm   = wid >> 1;
    const int wn   = wid & 1;
    const int m0   = blockIdx.y * 128;
    const int n0   = blockIdx.x * 128;

    // ldmatrix lane addressing: row = base + (lane&15), col = (lane>>4)*8
    const int lrow = lane & 15;
    const int lcol = (lane >> 4) << 3;

    float d[2][8][4];
#pragma unroll
    for (int mt = 0; mt < 2; mt++)
#pragma unroll
        for (int nt = 0; nt < 8; nt++)
#pragma unroll
            for (int r = 0; r < 4; r++) d[mt][nt][r] = 0.f;

    const int nchunk = K >> 5;                 // 32-wide chunks

    // prologue: stage 0
    stage_loads(sb, Ah, Al, Wh, Wl,
                (size_t)m0 * K, (size_t)n0 * K, K, tid);
    CP_COMMIT();

    for (int c = 0; c < nchunk; c++) {
        if (c + 1 < nchunk) {
            stage_loads(sb + ((c + 1) & 1) * (STAGE_ELEMS * 2),
                        Ah, Al, Wh, Wl,
                        (size_t)m0 * K + (c + 1) * 32,
                        (size_t)n0 * K + (c + 1) * 32, K, tid);
            CP_COMMIT();
            CP_WAIT(1);
        } else {
            CP_WAIT(0);
        }
        __syncthreads();

        const uint32_t st = sb + (c & 1) * (STAGE_ELEMS * 2);
        const uint32_t sAh = st;
        const uint32_t sAl = st + 1 * (GT_ELEMS * 2);
        const uint32_t sWh = st + 2 * (GT_ELEMS * 2);
        const uint32_t sWl = st + 3 * (GT_ELEMS * 2);

#pragma unroll
        for (int kk = 0; kk < 32; kk += 16) {
            uint32_t ah[2][4], al[2][4];
#pragma unroll
            for (int mt = 0; mt < 2; mt++) {
                uint32_t ra = (uint32_t)((wm * 32 + mt * 16 + lrow) * (LDT2 * 2)
                                         + (kk + lcol) * 2);
                LDSM_X4(ah[mt][0], ah[mt][1], ah[mt][2], ah[mt][3], sAh + ra);
                LDSM_X4(al[mt][0], al[mt][1], al[mt][2], al[mt][3], sAl + ra);
            }
#pragma unroll
            for (int ntp = 0; ntp < 4; ntp++) {
                uint32_t rb = (uint32_t)((wn * 64 + ntp * 16 + lrow) * (LDT2 * 2)
                                         + (kk + lcol) * 2);
                uint32_t bh[4], bl[4];
                LDSM_X4(bh[0], bh[1], bh[2], bh[3], sWh + rb);
                LDSM_X4(bl[0], bl[1], bl[2], bl[3], sWl + rb);
#pragma unroll
                for (int sub = 0; sub < 2; sub++) {
                    int nt = ntp * 2 + sub;
#pragma unroll
                    for (int mt = 0; mt < 2; mt++) {
                        MMA16816(d[mt][nt], ah[mt], bh[sub], bh[2 + sub]);
                        MMA16816(d[mt][nt], al[mt], bh[sub], bh[2 + sub]);
                        MMA16816(d[mt][nt], ah[mt], bl[sub], bl[2 + sub]);
                    }
                }
            }
        }
        __syncthreads();
    }

#pragma unroll
    for (int mt = 0; mt < 2; mt++) {
        int r0 = m0 + wm * 32 + mt * 16 + grp;
#pragma unroll
        for (int nt = 0; nt < 8; nt++) {
            int cc = n0 + wn * 64 + nt * 8 + tq * 2;
            float b0 = bias[cc], b1 = bias[cc + 1];
            float v00 = d[mt][nt][0] + b0, v01 = d[mt][nt][1] + b1;
            float v10 = d[mt][nt][2] + b0, v11 = d[mt][nt][3] + b1;
            if (mode & 1) {
                *(float2*)(C + (size_t)r0 * N + cc)       = make_float2(v00, v01);
                *(float2*)(C + (size_t)(r0 + 8) * N + cc) = make_float2(v10, v11);
            }
            if (mode & 2) {
                uint32_t h0 = pack_bf(v00, v01), h1 = pack_bf(v10, v11);
                uint32_t l0 = pack_bf(v00 - bfx2_lo(h0), v01 - bfx2_hi(h0));
                uint32_t l1 = pack_bf(v10 - bfx2_lo(h1), v11 - bfx2_hi(h1));
                *(uint32_t*)(Chi + (size_t)r0 * N + cc)       = h0;
                *(uint32_t*)(Chi + (size_t)(r0 + 8) * N + cc) = h1;
                *(uint32_t*)(Clo + (size_t)r0 * N + cc)       = l0;
                *(uint32_t*)(Clo + (size_t)(r0 + 8) * N + cc) = l1;
            }
        }
    }
}

// =================================================================
// Tensor-core attention (unchanged from R5): q-tile 64, 4 warps.
// =================================================================
#define ALDT 72
#define ATILE (64 * ALDT)
#define ATTN_SMEM (6 * ATILE * 2 + 64 * 4)

__global__ __launch_bounds__(128)
void attn_mma(const __nv_bfloat16* __restrict__ Qh, const __nv_bfloat16* __restrict__ Ql,
              const __nv_bfloat16* __restrict__ Kh, const __nv_bfloat16* __restrict__ Kl,
              const __nv_bfloat16* __restrict__ Vh, const __nv_bfloat16* __restrict__ Vl,
              const float* __restrict__ mult,
              __nv_bfloat16* __restrict__ Ohi, __nv_bfloat16* __restrict__ Olo)
{
    extern __shared__ __nv_bfloat16 smb[];
    __nv_bfloat16* sQh = smb;
    __nv_bfloat16* sQl = smb + ATILE;
    __nv_bfloat16* sKh = smb + 2 * ATILE;
    __nv_bfloat16* sKl = smb + 3 * ATILE;
    __nv_bfloat16* sVh = smb + 4 * ATILE;
    __nv_bfloat16* sVl = smb + 5 * ATILE;
    float* Lm = (float*)(smb + 6 * ATILE);

    const int tid  = threadIdx.x;
    const int wid  = tid >> 5;
    const int lane = tid & 31;
    const int grp  = lane >> 2;
    const int tq   = lane & 3;
    const int qb   = blockIdx.x;
    const int h    = blockIdx.y;
    const int b    = blockIdx.z;

    const size_t qoff  = ((size_t)(b * NQS + qb * 64)) * EMB + h * HD;
    const size_t kbase = ((size_t)b * NKS) * EMB + h * HD;

#pragma unroll
    for (int i = 0; i < 4; i++) {
        int idx = tid + i * 128;
        int r = idx >> 3, c8 = idx & 7;
        *(float4*)(sQh + r * ALDT + c8 * 8) = *(const float4*)(Qh + qoff + (size_t)r * EMB + c8 * 8);
        *(float4*)(sQl + r * ALDT + c8 * 8) = *(const float4*)(Ql + qoff + (size_t)r * EMB + c8 * 8);
    }
    __syncthreads();

    uint32_t aqh[4][4], aql[4][4];
#pragma unroll
    for (int ks = 0; ks < 4; ks++) {
        int r = wid * 16 + grp;
        int c = ks * 16 + tq * 2;
        aqh[ks][0] = ld_u32s(sQh + (r    ) * ALDT + c    );
        aqh[ks][1] = ld_u32s(sQh + (r + 8) * ALDT + c    );
        aqh[ks][2] = ld_u32s(sQh + (r    ) * ALDT + c + 8);
        aqh[ks][3] = ld_u32s(sQh + (r + 8) * ALDT + c + 8);
        aql[ks][0] = ld_u32s(sQl + (r    ) * ALDT + c    );
        aql[ks][1] = ld_u32s(sQl + (r + 8) * ALDT + c    );
        aql[ks][2] = ld_u32s(sQl + (r    ) * ALDT + c + 8);
        aql[ks][3] = ld_u32s(sQl + (r + 8) * ALDT + c + 8);
    }

    float dO[8][4];
#pragma unroll
    for (int nt = 0; nt < 8; nt++)
#pragma unroll
        for (int r = 0; r < 4; r++) dO[nt][r] = 0.f;
    float mrun0 = -3.4e38f, mrun1 = -3.4e38f, lrun0 = 0.f, lrun1 = 0.f;

    const uint32_t svh_base = smem_u32(sVh);
    const uint32_t svl_base = smem_u32(sVl);

    for (int k0 = 0; k0 < NKS; k0 += 64) {
        __syncthreads();
#pragma unroll
        for (int i = 0; i < 4; i++) {
            int idx = tid + i * 128;
            int r = idx >> 3, c8 = idx & 7;
            size_t src = kbase + (size_t)(k0 + r) * EMB + c8 * 8;
            *(float4*)(sKh + r * ALDT + c8 * 8) = *(const float4*)(Kh + src);
            *(float4*)(sKl + r * ALDT + c8 * 8) = *(const float4*)(Kl + src);
            *(float4*)(sVh + r * ALDT + c8 * 8) = *(const float4*)(Vh + src);
            *(float4*)(sVl + r * ALDT + c8 * 8) = *(const float4*)(Vl + src);
        }
        if (tid < 64) Lm[tid] = __logf(mult[b * NKS + k0 + tid]);
        __syncthreads();

        float dS[8][4];
#pragma unroll
        for (int nt = 0; nt < 8; nt++) {
#pragma unroll
            for (int r = 0; r < 4; r++) dS[nt][r] = 0.f;
#pragma unroll
            for (int ks = 0; ks < 4; ks++) {
                int n = nt * 8 + grp;
                int c = ks * 16 + tq * 2;
                uint32_t bh0 = ld_u32s(sKh + n * ALDT + c);
                uint32_t bh1 = ld_u32s(sKh + n * ALDT + c + 8);
                uint32_t bl0 = ld_u32s(sKl + n * ALDT + c);
                uint32_t bl1 = ld_u32s(sKl + n * ALDT + c + 8);
                MMA16816(dS[nt], aqh[ks], bh0, bh1);
                MMA16816(dS[nt], aql[ks], bh0, bh1);
                MMA16816(dS[nt], aqh[ks], bl0, bl1);
            }
        }

        float mx0 = -3.4e38f, mx1 = -3.4e38f;
#pragma unroll
        for (int nt = 0; nt < 8; nt++) {
            float lm0 = Lm[nt * 8 + tq * 2], lm1 = Lm[nt * 8 + tq * 2 + 1];
            dS[nt][0] = dS[nt][0] * 0.125f + lm0;
            dS[nt][1] = dS[nt][1] * 0.125f + lm1;
            dS[nt][2] = dS[nt][2] * 0.125f + lm0;
            dS[nt][3] = dS[nt][3] * 0.125f + lm1;
            mx0 = fmaxf(mx0, fmaxf(dS[nt][0], dS[nt][1]));
            mx1 = fmaxf(mx1, fmaxf(dS[nt][2], dS[nt][3]));
        }
        mx0 = fmaxf(mx0, __shfl_xor_sync(0xffffffffu, mx0, 1));
        mx0 = fmaxf(mx0, __shfl_xor_sync(0xffffffffu, mx0, 2));
        mx1 = fmaxf(mx1, __shfl_xor_sync(0xffffffffu, mx1, 1));
        mx1 = fmaxf(mx1, __shfl_xor_sync(0xffffffffu, mx1, 2));
        float mnew0 = fmaxf(mrun0, mx0), mnew1 = fmaxf(mrun1, mx1);
        float corr0 = __expf(mrun0 - mnew0), corr1 = __expf(mrun1 - mnew1);
        float rs0 = 0.f, rs1 = 0.f;
#pragma unroll
        for (int nt = 0; nt < 8; nt++) {
            dS[nt][0] = __expf(dS[nt][0] - mnew0); rs0 += dS[nt][0];
            dS[nt][1] = __expf(dS[nt][1] - mnew0); rs0 += dS[nt][1];
            dS[nt][2] = __expf(dS[nt][2] - mnew1); rs1 += dS[nt][2];
            dS[nt][3] = __expf(dS[nt][3] - mnew1); rs1 += dS[nt][3];
        }
        rs0 += __shfl_xor_sync(0xffffffffu, rs0, 1);
        rs0 += __shfl_xor_sync(0xffffffffu, rs0, 2);
        rs1 += __shfl_xor_sync(0xffffffffu, rs1, 1);
        rs1 += __shfl_xor_sync(0xffffffffu, rs1, 2);
        lrun0 = lrun0 * corr0 + rs0; mrun0 = mnew0;
        lrun1 = lrun1 * corr1 + rs1; mrun1 = mnew1;
#pragma unroll
        for (int nt = 0; nt < 8; nt++) {
            dO[nt][0] *= corr0; dO[nt][1] *= corr0;
            dO[nt][2] *= corr1; dO[nt][3] *= corr1;
        }

#pragma unroll
        for (int kb = 0; kb < 4; kb++) {
            uint32_t ph[4], pl[4];
            ph[0] = pack_bf(dS[2 * kb][0],     dS[2 * kb][1]);
            ph[1] = pack_bf(dS[2 * kb][2],     dS[2 * kb][3]);
            ph[2] = pack_bf(dS[2 * kb + 1][0], dS[2 * kb + 1][1]);
            ph[3] = pack_bf(dS[2 * kb + 1][2], dS[2 * kb + 1][3]);
            pl[0] = pack_bf(dS[2 * kb][0] - bfx2_lo(ph[0]),     dS[2 * kb][1] - bfx2_hi(ph[0]));
            pl[1] = pack_bf(dS[2 * kb][2] - bfx2_lo(ph[1]),     dS[2 * kb][3] - bfx2_hi(ph[1]));
            pl[2] = pack_bf(dS[2 * kb + 1][0] - bfx2_lo(ph[2]), dS[2 * kb + 1][1] - bfx2_hi(ph[2]));
            pl[3] = pack_bf(dS[2 * kb + 1][2] - bfx2_lo(ph[3]), dS[2 * kb + 1][3] - bfx2_hi(ph[3]));

#pragma unroll
            for (int np = 0; np < 4; np++) {
                int krow = kb * 16 + (lane & 15);
                int ncol = np * 16 + ((lane >> 4) << 3);
                uint32_t off = (uint32_t)(krow * ALDT + ncol) * 2;
                uint32_t vh[4], vl[4];
                LDSM_X4_T(vh[0], vh[1], vh[2], vh[3], svh_base + off);
                LDSM_X4_T(vl[0], vl[1], vl[2], vl[3], svl_base + off);
                MMA16816(dO[2 * np],     ph, vh[0], vh[1]);
                MMA16816(dO[2 * np],     pl, vh[0], vh[1]);
                MMA16816(dO[2 * np],     ph, vl[0], vl[1]);
                MMA16816(dO[2 * np + 1], ph, vh[2], vh[3]);
                MMA16816(dO[2 * np + 1], pl, vh[2], vh[3]);
                MMA16816(dO[2 * np + 1], ph, vl[2], vl[3]);
            }
        }
    }

    float inv0 = 1.f / lrun0, inv1 = 1.f / lrun1;
    int gr0 = qb * 64 + wid * 16 + grp;
#pragma unroll
    for (int nt = 0; nt < 8; nt++) {
        int col = h * HD + nt * 8 + tq * 2;
        float o00 = dO[nt][0] * inv0, o01 = dO[nt][1] * inv0;
        float o10 = dO[nt][2] * inv1, o11 = dO[nt][3] * inv1;
        uint32_t h0 = pack_bf(o00, o01), h1 = pack_bf(o10, o11);
        uint32_t l0 = pack_bf(o00 - bfx2_lo(h0), o01 - bfx2_hi(h0));
        uint32_t l1 = pack_bf(o10 - bfx2_lo(h1), o11 - bfx2_hi(h1));
        size_t p0 = ((size_t)(b * NQS + gr0)) * EMB + col;
        size_t p1 = ((size_t)(b * NQS + gr0 + 8)) * EMB + col;
        *(uint32_t*)(Ohi + p0) = h0; *(uint32_t*)(Ohi + p1) = h1;
        *(uint32_t*)(Olo + p0) = l0; *(uint32_t*)(Olo + p1) = l1;
    }
}

// =================================================================
extern "C" void kernel_launch(void* const* d_in, const int* in_sizes, int n_in,
                              void* d_out, int out_size)
{
    const float* query = (const float*)d_in[0];
    const float* key_  = (const float*)d_in[1];
    const float* value = (const float*)d_in[2];
    const float* mult  = (const float*)d_in[3];
    const float* wq_w  = (const float*)d_in[4];
    const float* wq_b  = (const float*)d_in[5];
    const float* wk_w  = (const float*)d_in[6];
    const float* wk_b  = (const float*)d_in[7];
    const float* wv_w  = (const float*)d_in[8];
    const float* wv_b  = (const float*)d_in[9];
    const float* wo_w  = (const float*)d_in[10];
    const float* wo_b  = (const float*)d_in[11];
    float* out = (float*)d_out;

    __nv_bfloat16 *qh, *ql, *kh, *kl, *vh, *vl, *wh, *wl;
    __nv_bfloat16 *pqh, *pql, *pkh, *pkl, *pvh, *pvl, *aoh, *aol;
    cudaGetSymbolAddress((void**)&qh,  g_qh);
    cudaGetSymbolAddress((void**)&ql,  g_ql);
    cudaGetSymbolAddress((void**)&kh,  g_kh);
    cudaGetSymbolAddress((void**)&kl,  g_kl);
    cudaGetSymbolAddress((void**)&vh,  g_vh);
    cudaGetSymbolAddress((void**)&vl,  g_vl);
    cudaGetSymbolAddress((void**)&wh,  g_wh);
    cudaGetSymbolAddress((void**)&wl,  g_wl);
    cudaGetSymbolAddress((void**)&pqh, g_pqh);
    cudaGetSymbolAddress((void**)&pql, g_pql);
    cudaGetSymbolAddress((void**)&pkh, g_pkh);
    cudaGetSymbolAddress((void**)&pkl, g_pkl);
    cudaGetSymbolAddress((void**)&pvh, g_pvh);
    cudaGetSymbolAddress((void**)&pvl, g_pvl);
    cudaGetSymbolAddress((void**)&aoh, g_aoh);
    cudaGetSymbolAddress((void**)&aol, g_aol);

    cudaFuncSetAttribute(gemm_bf16x3,
                         cudaFuncAttributeMaxDynamicSharedMemorySize, G_SMEM2);
    cudaFuncSetAttribute(attn_mma,
                         cudaFuncAttributeMaxDynamicSharedMemorySize, ATTN_SMEM);

    const size_t WSZ = (size_t)EMB * EMB;
    const int nq4 = BB * NQS * EMB / 4, nk4 = BB * NKS * EMB / 4, nw4 = (int)(WSZ / 4);

    split_kernel<<<(nq4 + 255) / 256, 256>>>(query, qh, ql, nq4);
    split_kernel<<<(nk4 + 255) / 256, 256>>>(key_,  kh, kl, nk4);
    split_kernel<<<(nk4 + 255) / 256, 256>>>(value, vh, vl, nk4);
    split_kernel<<<(nw4 + 255) / 256, 256>>>(wq_w, wh + 0 * WSZ, wl + 0 * WSZ, nw4);
    split_kernel<<<(nw4 + 255) / 256, 256>>>(wk_w, wh + 1 * WSZ, wl + 1 * WSZ, nw4);
    split_kernel<<<(nw4 + 255) / 256, 256>>>(wv_w, wh + 2 * WSZ, wl + 2 * WSZ, nw4);
    split_kernel<<<(nw4 + 255) / 256, 256>>>(wo_w, wh + 3 * WSZ, wl + 3 * WSZ, nw4);

    dim3 gq(EMB / 128, (BB * NQS) / 128);   // (8, 32)
    dim3 gk(EMB / 128, (BB * NKS) / 128);   // (8, 64)

    gemm_bf16x3<<<gq, 256, G_SMEM2>>>(qh, ql, wh + 0 * WSZ, wl + 0 * WSZ, wq_b,
                                      out, pqh, pql, BB * NQS, EMB, EMB, 2);
    gemm_bf16x3<<<gk, 256, G_SMEM2>>>(kh, kl, wh + 1 * WSZ, wl + 1 * WSZ, wk_b,
                                      out, pkh, pkl, BB * NKS, EMB, EMB, 2);
    gemm_bf16x3<<<gk, 256, G_SMEM2>>>(vh, vl, wh + 2 * WSZ, wl + 2 * WSZ, wv_b,
                                      out, pvh, pvl, BB * NKS, EMB, EMB, 2);

    dim3 ga(NQS / 64, NH, BB);              // (16, 16, 4)
    attn_mma<<<ga, 128, ATTN_SMEM>>>(pqh, pql, pkh, pkl, pvh, pvl, mult, aoh, aol);

    gemm_bf16x3<<<gq, 256, G_SMEM2>>>(aoh, aol, wh + 3 * WSZ, wl + 3 * WSZ, wo_b,
                                      out, aoh, aol, BB * NQS, EMB, EMB, 1);
}